// round 7
// baseline (speedup 1.0000x reference)
#include <cuda_runtime.h>
#include <stdint.h>

// ============================================================================
// Exact VQ argmin via packed fp32x2 FMA (SASS FFMA2, 2 MAC/instr).
// R7 = R6 with the A-fill bug fixed (CP16 copies 16 BYTES; need 28 per row,
//      not 7): 112-token tiles -> 147 CTAs (99% SM fill), DC=32 chunks,
//      stride-16 token microtile (7 tok x 16 codes/thread).
//   prep:  cbT[d][code] transpose; csqh = -0.5*||c||^2
//   sweep: acc(init=csqh) += x*c via fma.rn.f32x2; argmax == argmin dist.
//   gather: out = codebook[idx]
// ============================================================================

#define NTOK   16384
#define DIM    256
#define HW     1024
#define KCODES 4096
#define MTILE  112
#define NCTA   147              // ceil(16384/112)
#define CTILE  256              // codes per tile
#define DC     32               // dims per chunk
#define NCHUNK ((KCODES / CTILE) * (DIM / DC))   // 16 * 8 = 128

// smem (bytes)
#define SM_A    0                 // 256 d x 112 tok x 4B = 114688
#define SM_B    114688            // 2 x 32 d x 1024B     = 65536
#define SM_Q    180224            // csqh 4096 f32        = 16384
#define SM_BEST 196608            // 128 u64
#define SM_TOT  197632

__device__ float g_cbT[DIM * KCODES];   // [d][code]
__device__ float g_csqh[KCODES];        // -0.5*||c||^2
__device__ int   g_idx[NTOK];

typedef unsigned long long u64;
__device__ __forceinline__ uint32_t smem_u32(const void* p) {
    uint32_t a;
    asm("{ .reg .u64 t; cvta.to.shared.u64 t, %1; cvt.u32.u64 %0, t; }" : "=r"(a) : "l"(p));
    return a;
}
__device__ __forceinline__ unsigned ford(float f) {
    unsigned u = __float_as_uint(f);
    return (u & 0x80000000u) ? ~u : (u | 0x80000000u);
}
__device__ __forceinline__ u64 pack2(float v) {
    u64 r; unsigned b = __float_as_uint(v);
    asm("mov.b64 %0, {%1, %1};" : "=l"(r) : "r"(b));
    return r;
}
__device__ __forceinline__ void fma2(u64& acc, u64 a, u64 b) {
    asm("fma.rn.f32x2 %0, %1, %2, %0;" : "+l"(acc) : "l"(a), "l"(b));
}
__device__ __forceinline__ void lds_v2u64(u64& r0, u64& r1, uint32_t a) {
    asm volatile("ld.shared.v2.u64 {%0,%1}, [%2];" : "=l"(r0), "=l"(r1) : "r"(a));
}
#define CP16(d, s)  asm volatile("cp.async.cg.shared.global [%0], [%1], 16;" :: "r"(d), "l"(s))
#define CPCOMMIT()  asm volatile("cp.async.commit_group;" ::: "memory")
#define CPWAIT1()   asm volatile("cp.async.wait_group 1;" ::: "memory")
#define CPWAIT0()   asm volatile("cp.async.wait_group 0;" ::: "memory")

// ---------------- prep ----------------
__global__ __launch_bounds__(256) void tr_kernel(const float* __restrict__ cb) {
    __shared__ float t[32][33];
    const int c0 = blockIdx.x * 32, d0 = blockIdx.y * 32;
    const int tx = threadIdx.x & 31, ty8 = threadIdx.x >> 5;
#pragma unroll
    for (int r = 0; r < 4; r++)
        t[ty8 + r * 8][tx] = cb[(size_t)(c0 + ty8 + r * 8) * DIM + d0 + tx];
    __syncthreads();
#pragma unroll
    for (int r = 0; r < 4; r++)
        g_cbT[(size_t)(d0 + ty8 + r * 8) * KCODES + c0 + tx] = t[tx][ty8 + r * 8];
}
__global__ __launch_bounds__(256) void csqh_kernel(const float* __restrict__ cb) {
    const int code = blockIdx.x * 8 + (threadIdx.x >> 5);
    const int lane = threadIdx.x & 31;
    const float* row = cb + (size_t)code * DIM;
    float s = 0.f;
#pragma unroll
    for (int i = 0; i < 8; i++) { float v = row[lane + 32 * i]; s = fmaf(v, v, s); }
#pragma unroll
    for (int o = 16; o > 0; o >>= 1) s += __shfl_xor_sync(0xFFFFFFFFu, s, o);
    if (lane == 0) g_csqh[code] = -0.5f * s;
}

// ---------------- main sweep ----------------
__global__ __launch_bounds__(256, 1) void sweep_kernel(const float* __restrict__ x) {
    extern __shared__ char sm[];
    float* Af     = reinterpret_cast<float*>(sm + SM_A);   // [d][112]
    float* csqh_s = reinterpret_cast<float*>(sm + SM_Q);
    u64*   sbest  = reinterpret_cast<u64*>(sm + SM_BEST);
    const uint32_t sb = smem_u32(sm);

    const int tid = threadIdx.x;
    const int tx  = tid & 15;       // code group: 16 codes
    const int ty  = tid >> 4;       // token slot: tokens ty + 16*m
    const int n0  = blockIdx.x * MTILE;

    // ---- A fill: one d-row per thread, 28 x 16B cp.async, batch-split ----
    {
        const int pos0 = n0 & (HW - 1);
        const int b0   = n0 >> 10;
        const int len1 = min(MTILE, HW - pos0);          // multiple of 16
        const int d    = tid;
        const uint32_t dst = sb + SM_A + d * (MTILE * 4);
#pragma unroll
        for (int c = 0; c < 28; c++) {
            const int col0 = c * 4;                      // 4 tokens = 16 bytes
            if (col0 < len1) {
                const float* src = x + ((size_t)b0 * DIM + d) * HW + pos0 + col0;
                CP16(dst + col0 * 4, src);
            } else if (b0 + 1 < 16) {
                const float* src = x + ((size_t)(b0 + 1) * DIM + d) * HW + (col0 - len1);
                CP16(dst + col0 * 4, src);
            }
        }
        CPCOMMIT();
    }
    for (int i = tid; i < KCODES; i += 256) csqh_s[i] = g_csqh[i];
    if (tid < MTILE + 16) sbest[tid] = 0ull;
    // ---- B chunk 0 ----
    {
        const char* src = reinterpret_cast<const char*>(g_cbT);
        for (int k = 0; k < 8; k++) {
            int s = tid + k * 256;                 // 2048 x 16B
            int r = s >> 6, c = s & 63;
            CP16(sb + SM_B + r * 1024 + c * 16,
                 src + (size_t)r * (KCODES * 4) + c * 16);
        }
        CPCOMMIT();
    }

    float bestv[7];
    int   bestc[7];
#pragma unroll
    for (int i = 0; i < 7; i++) { bestv[i] = -3.4e38f; bestc[i] = 0; }

    u64 acc[7][8];

    for (int cidx = 0; cidx < NCHUNK; cidx++) {
        const int ct  = cidx >> 3;
        const int dcc = cidx & 7;
        const int p   = cidx & 1;

        // prefetch next chunk
        if (cidx + 1 < NCHUNK) {
            const int nct = (cidx + 1) >> 3, ndc = (cidx + 1) & 7;
            const char* src = reinterpret_cast<const char*>(
                g_cbT + (size_t)(ndc * DC) * KCODES + nct * CTILE);
            const uint32_t dst = sb + SM_B + ((cidx + 1) & 1) * 32768;
            for (int k = 0; k < 8; k++) {
                int s = tid + k * 256;
                int r = s >> 6, c = s & 63;
                CP16(dst + r * 1024 + c * 16, src + (size_t)r * (KCODES * 4) + c * 16);
            }
            CPCOMMIT();
            CPWAIT1();
        } else {
            CPWAIT0();
        }
        __syncthreads();

        // acc init at tile start
        if (dcc == 0) {
            const int qb = ct * CTILE + tx * 16;
            u64 k8[8];
#pragma unroll
            for (int j = 0; j < 8; j++)
                k8[j] = *reinterpret_cast<const u64*>(csqh_s + qb + 2 * j);
#pragma unroll
            for (int i = 0; i < 7; i++)
#pragma unroll
                for (int j = 0; j < 8; j++) acc[i][j] = k8[j];
        }

        // ---- compute 32 d-steps ----
        const float*   Abase = Af + dcc * DC * MTILE + ty;
        const uint32_t Bbase = sb + SM_B + p * 32768 + tx * 64;
#pragma unroll 4
        for (int k = 0; k < DC; k++) {
            u64 pa[7];
#pragma unroll
            for (int m = 0; m < 7; m++)
                pa[m] = pack2(Abase[k * MTILE + 16 * m]);
            u64 bb[8];
#pragma unroll
            for (int s = 0; s < 4; s++)
                lds_v2u64(bb[s * 2], bb[s * 2 + 1], Bbase + k * 1024 + s * 16);
#pragma unroll
            for (int i = 0; i < 7; i++)
#pragma unroll
                for (int j = 0; j < 8; j++)
                    fma2(acc[i][j], pa[i], bb[j]);
        }
        __syncthreads();

        // ---- tile epilogue: running argmax ----
        if (dcc == 7) {
            const int cb0 = ct * CTILE + tx * 16;
#pragma unroll
            for (int i = 0; i < 7; i++)
#pragma unroll
                for (int j = 0; j < 8; j++) {
                    unsigned lo, hi;
                    asm("mov.b64 {%0,%1}, %2;" : "=r"(lo), "=r"(hi) : "l"(acc[i][j]));
                    float v0 = __uint_as_float(lo), v1 = __uint_as_float(hi);
                    int c = cb0 + 2 * j;
                    if (v0 > bestv[i]) { bestv[i] = v0; bestc[i] = c; }
                    if (v1 > bestv[i]) { bestv[i] = v1; bestc[i] = c + 1; }
                }
        }
    }

    // ---- cross-thread reduction: max value, then min code ----
#pragma unroll
    for (int i = 0; i < 7; i++) {
        u64 key = ((u64)ford(bestv[i]) << 32) | (u64)(0xFFFFFFFFu - (unsigned)bestc[i]);
        atomicMax(&sbest[ty + 16 * i], key);
    }
    __syncthreads();
    if (tid < MTILE && n0 + tid < NTOK) {
        unsigned low = (unsigned)(sbest[tid] & 0xFFFFFFFFull);
        g_idx[n0 + tid] = (int)(0xFFFFFFFFu - low);
    }
}

// ---------------- gather ----------------
__global__ void gather_kernel(const float* __restrict__ cb, float* __restrict__ out) {
    int o = blockIdx.x * blockDim.x + threadIdx.x;
    int p = o & (HW - 1);
    int d = (o >> 10) & (DIM - 1);
    int b = o >> 18;
    int n = (b << 10) + p;
    out[o] = cb[(size_t)g_idx[n] * DIM + d];
}

extern "C" void kernel_launch(void* const* d_in, const int* in_sizes, int n_in,
                              void* d_out, int out_size) {
    const float* x  = (const float*)d_in[0];
    const float* cb = (const float*)d_in[1];
    float* out = (float*)d_out;

    cudaFuncSetAttribute(sweep_kernel, cudaFuncAttributeMaxDynamicSharedMemorySize, SM_TOT);

    tr_kernel<<<dim3(KCODES / 32, DIM / 32), 256>>>(cb);
    csqh_kernel<<<KCODES / 8, 256>>>(cb);
    sweep_kernel<<<NCTA, 256, SM_TOT>>>(x);
    gather_kernel<<<(NTOK * DIM) / 256, 256>>>(cb, out);
}

// round 8
// speedup vs baseline: 1.6940x; 1.6940x over previous
#include <cuda_runtime.h>
#include <stdint.h>

// ============================================================================
// Exact VQ argmin via packed fp32x2 FMA (SASS FFMA2, 2 MAC/instr).
// R8 = R5 microtile/B-layout (conflict-free LDS) + 112-token tiles (147 CTAs,
//      99.3% SM fill). 7 tok x 16 codes per thread; codes tx*4 + s*64 + q*2.
//   prep:  cbT[d][code] transpose; csqh = -0.5*||c||^2
//   sweep: acc(init=csqh) += x*c via fma.rn.f32x2; argmax == argmin dist.
//   gather: out = codebook[idx]
// ============================================================================

#define NTOK   16384
#define DIM    256
#define HW     1024
#define KCODES 4096
#define MTILE  112
#define NCTA   147              // ceil(16384/112)
#define CTILE  256              // codes per tile
#define DC     16               // dims per chunk
#define NCHUNK ((KCODES / CTILE) * (DIM / DC))   // 16 * 16 = 256

// smem (bytes)
#define SM_A    0                 // 256 d x 112 tok x 4B = 114688
#define SM_B    114688            // 2 x 16 d x 1024B     = 32768
#define SM_Q    147456            // csqh 4096 f32        = 16384
#define SM_BEST 163840            // 112 u64 (+pad)
#define SM_TOT  164864

__device__ float g_cbT[DIM * KCODES];   // [d][code]
__device__ float g_csqh[KCODES];        // -0.5*||c||^2
__device__ int   g_idx[NTOK];

typedef unsigned long long u64;
__device__ __forceinline__ uint32_t smem_u32(const void* p) {
    uint32_t a;
    asm("{ .reg .u64 t; cvta.to.shared.u64 t, %1; cvt.u32.u64 %0, t; }" : "=r"(a) : "l"(p));
    return a;
}
__device__ __forceinline__ unsigned ford(float f) {
    unsigned u = __float_as_uint(f);
    return (u & 0x80000000u) ? ~u : (u | 0x80000000u);
}
__device__ __forceinline__ u64 pack2(float v) {
    u64 r; unsigned b = __float_as_uint(v);
    asm("mov.b64 %0, {%1, %1};" : "=l"(r) : "r"(b));
    return r;
}
__device__ __forceinline__ void fma2(u64& acc, u64 a, u64 b) {
    asm("fma.rn.f32x2 %0, %1, %2, %0;" : "+l"(acc) : "l"(a), "l"(b));
}
__device__ __forceinline__ void lds_v2u64(u64& r0, u64& r1, uint32_t a) {
    asm volatile("ld.shared.v2.u64 {%0,%1}, [%2];" : "=l"(r0), "=l"(r1) : "r"(a));
}
#define CP16(d, s)  asm volatile("cp.async.cg.shared.global [%0], [%1], 16;" :: "r"(d), "l"(s))
#define CPCOMMIT()  asm volatile("cp.async.commit_group;" ::: "memory")
#define CPWAIT1()   asm volatile("cp.async.wait_group 1;" ::: "memory")
#define CPWAIT0()   asm volatile("cp.async.wait_group 0;" ::: "memory")

// ---------------- prep ----------------
__global__ __launch_bounds__(256) void tr_kernel(const float* __restrict__ cb) {
    __shared__ float t[32][33];
    const int c0 = blockIdx.x * 32, d0 = blockIdx.y * 32;
    const int tx = threadIdx.x & 31, ty8 = threadIdx.x >> 5;
#pragma unroll
    for (int r = 0; r < 4; r++)
        t[ty8 + r * 8][tx] = cb[(size_t)(c0 + ty8 + r * 8) * DIM + d0 + tx];
    __syncthreads();
#pragma unroll
    for (int r = 0; r < 4; r++)
        g_cbT[(size_t)(d0 + ty8 + r * 8) * KCODES + c0 + tx] = t[tx][ty8 + r * 8];
}
__global__ __launch_bounds__(256) void csqh_kernel(const float* __restrict__ cb) {
    const int code = blockIdx.x * 8 + (threadIdx.x >> 5);
    const int lane = threadIdx.x & 31;
    const float* row = cb + (size_t)code * DIM;
    float s = 0.f;
#pragma unroll
    for (int i = 0; i < 8; i++) { float v = row[lane + 32 * i]; s = fmaf(v, v, s); }
#pragma unroll
    for (int o = 16; o > 0; o >>= 1) s += __shfl_xor_sync(0xFFFFFFFFu, s, o);
    if (lane == 0) g_csqh[code] = -0.5f * s;
}

// ---------------- main sweep ----------------
__global__ __launch_bounds__(256, 1) void sweep_kernel(const float* __restrict__ x) {
    extern __shared__ char sm[];
    float* Af     = reinterpret_cast<float*>(sm + SM_A);   // [d][112]
    float* csqh_s = reinterpret_cast<float*>(sm + SM_Q);
    u64*   sbest  = reinterpret_cast<u64*>(sm + SM_BEST);
    const uint32_t sb = smem_u32(sm);

    const int tid = threadIdx.x;
    const int tx  = tid & 15;       // code group (codes tx*4 + s*64 + q*2 .. +1)
    const int ty  = tid >> 4;       // token slot: tokens ty + 16*m, m<7
    const int n0  = blockIdx.x * MTILE;

    // ---- A fill: one d-row per thread, 28 x 16B cp.async, batch-split ----
    {
        const int pos0 = n0 & (HW - 1);
        const int b0   = n0 >> 10;
        const int len1 = min(MTILE, HW - pos0);          // multiple of 16
        const int d    = tid;
        const uint32_t dst = sb + SM_A + d * (MTILE * 4);
#pragma unroll
        for (int c = 0; c < 28; c++) {
            const int col0 = c * 4;                      // 4 tokens = 16 bytes
            if (col0 < len1) {
                const float* src = x + ((size_t)b0 * DIM + d) * HW + pos0 + col0;
                CP16(dst + col0 * 4, src);
            } else if (b0 + 1 < 16) {
                const float* src = x + ((size_t)(b0 + 1) * DIM + d) * HW + (col0 - len1);
                CP16(dst + col0 * 4, src);
            }
        }
        CPCOMMIT();
    }
    for (int i = tid; i < KCODES; i += 256) csqh_s[i] = g_csqh[i];
    if (tid < MTILE) sbest[tid] = 0ull;
    // ---- B chunk 0: 16 d-rows x 1024B ----
    {
        const char* src = reinterpret_cast<const char*>(g_cbT);
        for (int k = 0; k < 4; k++) {
            int s = tid + k * 256;                 // 1024 x 16B
            int r = s >> 6, c = s & 63;
            CP16(sb + SM_B + r * 1024 + c * 16,
                 src + (size_t)r * (KCODES * 4) + c * 16);
        }
        CPCOMMIT();
    }

    float bestv[7];
    int   bestc[7];
#pragma unroll
    for (int i = 0; i < 7; i++) { bestv[i] = -3.4e38f; bestc[i] = 0; }

    u64 acc[7][8];

    for (int cidx = 0; cidx < NCHUNK; cidx++) {
        const int ct = cidx >> 4;
        const int dc = cidx & 15;
        const int p  = cidx & 1;

        // prefetch next chunk
        if (cidx + 1 < NCHUNK) {
            const int nct = (cidx + 1) >> 4, ndc = (cidx + 1) & 15;
            const char* src = reinterpret_cast<const char*>(
                g_cbT + (size_t)(ndc * DC) * KCODES + nct * CTILE);
            const uint32_t dst = sb + SM_B + ((cidx + 1) & 1) * 16384;
            for (int k = 0; k < 4; k++) {
                int s = tid + k * 256;
                int r = s >> 6, c = s & 63;
                CP16(dst + r * 1024 + c * 16, src + (size_t)r * (KCODES * 4) + c * 16);
            }
            CPCOMMIT();
            CPWAIT1();
        } else {
            CPWAIT0();
        }
        __syncthreads();

        // acc init at tile start: -0.5*||c||^2 pairs (codes tx*4 + s*64 + q*2)
        if (dc == 0) {
            const int qb = ct * CTILE + tx * 4;
            u64 k8[8];
#pragma unroll
            for (int s = 0; s < 4; s++) {
                k8[s * 2]     = *reinterpret_cast<const u64*>(csqh_s + qb + s * 64);
                k8[s * 2 + 1] = *reinterpret_cast<const u64*>(csqh_s + qb + s * 64 + 2);
            }
#pragma unroll
            for (int i = 0; i < 7; i++)
#pragma unroll
                for (int j = 0; j < 8; j++) acc[i][j] = k8[j];
        }

        // ---- compute 16 d-steps ----
        const float*   Abase = Af + dc * DC * MTILE + ty;
        const uint32_t Bbase = sb + SM_B + p * 16384 + tx * 16;
#pragma unroll 4
        for (int k = 0; k < DC; k++) {
            u64 pa[7];
#pragma unroll
            for (int m = 0; m < 7; m++)
                pa[m] = pack2(Abase[k * MTILE + 16 * m]);
            u64 bb[8];
#pragma unroll
            for (int s = 0; s < 4; s++)
                lds_v2u64(bb[s * 2], bb[s * 2 + 1], Bbase + k * 1024 + s * 256);
#pragma unroll
            for (int i = 0; i < 7; i++)
#pragma unroll
                for (int j = 0; j < 8; j++)
                    fma2(acc[i][j], pa[i], bb[j]);
        }
        __syncthreads();

        // ---- tile epilogue: running argmax ----
        if (dc == 15) {
            const int cb0 = ct * CTILE + tx * 4;
#pragma unroll
            for (int i = 0; i < 7; i++)
#pragma unroll
                for (int s = 0; s < 4; s++)
#pragma unroll
                    for (int q = 0; q < 2; q++) {
                        unsigned lo, hi;
                        asm("mov.b64 {%0,%1}, %2;" : "=r"(lo), "=r"(hi) : "l"(acc[i][s * 2 + q]));
                        float v0 = __uint_as_float(lo), v1 = __uint_as_float(hi);
                        int c = cb0 + s * 64 + q * 2;
                        if (v0 > bestv[i]) { bestv[i] = v0; bestc[i] = c; }
                        if (v1 > bestv[i]) { bestv[i] = v1; bestc[i] = c + 1; }
                    }
        }
    }

    // ---- cross-thread reduction: max value, then min code ----
#pragma unroll
    for (int i = 0; i < 7; i++) {
        u64 key = ((u64)ford(bestv[i]) << 32) | (u64)(0xFFFFFFFFu - (unsigned)bestc[i]);
        atomicMax(&sbest[ty + 16 * i], key);
    }
    __syncthreads();
    if (tid < MTILE && n0 + tid < NTOK) {
        unsigned low = (unsigned)(sbest[tid] & 0xFFFFFFFFull);
        g_idx[n0 + tid] = (int)(0xFFFFFFFFu - low);
    }
}

// ---------------- gather ----------------
__global__ void gather_kernel(const float* __restrict__ cb, float* __restrict__ out) {
    int o = blockIdx.x * blockDim.x + threadIdx.x;
    int p = o & (HW - 1);
    int d = (o >> 10) & (DIM - 1);
    int b = o >> 18;
    int n = (b << 10) + p;
    out[o] = cb[(size_t)g_idx[n] * DIM + d];
}

extern "C" void kernel_launch(void* const* d_in, const int* in_sizes, int n_in,
                              void* d_out, int out_size) {
    const float* x  = (const float*)d_in[0];
    const float* cb = (const float*)d_in[1];
    float* out = (float*)d_out;

    cudaFuncSetAttribute(sweep_kernel, cudaFuncAttributeMaxDynamicSharedMemorySize, SM_TOT);

    tr_kernel<<<dim3(KCODES / 32, DIM / 32), 256>>>(cb);
    csqh_kernel<<<KCODES / 8, 256>>>(cb);
    sweep_kernel<<<NCTA, 256, SM_TOT>>>(x);
    gather_kernel<<<(NTOK * DIM) / 256, 256>>>(cb, out);
}

// round 9
// speedup vs baseline: 1.8173x; 1.0728x over previous
#include <cuda_runtime.h>
#include <stdint.h>

// ============================================================================
// Exact VQ argmin via packed fp32x2 FMA (SASS FFMA2, 2 MAC/instr).
// R9 = R8 + DC=32 chunks + 3-stage B pipeline with prefetch-2-ahead and a
//      SINGLE barrier per chunk (512 -> 128 barrier rounds).
//   prep:  cbT[d][code] transpose; csqh = -0.5*||c||^2
//   sweep: acc(init=csqh) += x*c via fma.rn.f32x2; argmax == argmin dist.
//   gather: out = codebook[idx]
// ============================================================================

#define NTOK   16384
#define DIM    256
#define HW     1024
#define KCODES 4096
#define MTILE  112
#define NCTA   147              // ceil(16384/112)
#define CTILE  256              // codes per tile
#define DC     32               // dims per chunk
#define NCHUNK ((KCODES / CTILE) * (DIM / DC))   // 16 * 8 = 128
#define BSTG   32768            // one B stage: 32 d x 1024B

// smem (bytes)
#define SM_A    0                 // 256 d x 112 tok x 4B = 114688
#define SM_B    114688            // 3 x 32768 = 98304
#define SM_Q    212992            // csqh 4096 f32 = 16384
#define SM_BEST 229376            // 112 u64 (+pad)
#define SM_TOT  230400

__device__ float g_cbT[DIM * KCODES];   // [d][code]
__device__ float g_csqh[KCODES];        // -0.5*||c||^2
__device__ int   g_idx[NTOK];

typedef unsigned long long u64;
__device__ __forceinline__ uint32_t smem_u32(const void* p) {
    uint32_t a;
    asm("{ .reg .u64 t; cvta.to.shared.u64 t, %1; cvt.u32.u64 %0, t; }" : "=r"(a) : "l"(p));
    return a;
}
__device__ __forceinline__ unsigned ford(float f) {
    unsigned u = __float_as_uint(f);
    return (u & 0x80000000u) ? ~u : (u | 0x80000000u);
}
__device__ __forceinline__ u64 pack2(float v) {
    u64 r; unsigned b = __float_as_uint(v);
    asm("mov.b64 %0, {%1, %1};" : "=l"(r) : "r"(b));
    return r;
}
__device__ __forceinline__ void fma2(u64& acc, u64 a, u64 b) {
    asm("fma.rn.f32x2 %0, %1, %2, %0;" : "+l"(acc) : "l"(a), "l"(b));
}
__device__ __forceinline__ void lds_v2u64(u64& r0, u64& r1, uint32_t a) {
    asm volatile("ld.shared.v2.u64 {%0,%1}, [%2];" : "=l"(r0), "=l"(r1) : "r"(a));
}
#define CP16(d, s)  asm volatile("cp.async.cg.shared.global [%0], [%1], 16;" :: "r"(d), "l"(s))
#define CPCOMMIT()  asm volatile("cp.async.commit_group;" ::: "memory")
#define CPWAIT1()   asm volatile("cp.async.wait_group 1;" ::: "memory")
#define CPWAIT0()   asm volatile("cp.async.wait_group 0;" ::: "memory")

// ---------------- prep ----------------
__global__ __launch_bounds__(256) void tr_kernel(const float* __restrict__ cb) {
    __shared__ float t[32][33];
    const int c0 = blockIdx.x * 32, d0 = blockIdx.y * 32;
    const int tx = threadIdx.x & 31, ty8 = threadIdx.x >> 5;
#pragma unroll
    for (int r = 0; r < 4; r++)
        t[ty8 + r * 8][tx] = cb[(size_t)(c0 + ty8 + r * 8) * DIM + d0 + tx];
    __syncthreads();
#pragma unroll
    for (int r = 0; r < 4; r++)
        g_cbT[(size_t)(d0 + ty8 + r * 8) * KCODES + c0 + tx] = t[tx][ty8 + r * 8];
}
__global__ __launch_bounds__(256) void csqh_kernel(const float* __restrict__ cb) {
    const int code = blockIdx.x * 8 + (threadIdx.x >> 5);
    const int lane = threadIdx.x & 31;
    const float* row = cb + (size_t)code * DIM;
    float s = 0.f;
#pragma unroll
    for (int i = 0; i < 8; i++) { float v = row[lane + 32 * i]; s = fmaf(v, v, s); }
#pragma unroll
    for (int o = 16; o > 0; o >>= 1) s += __shfl_xor_sync(0xFFFFFFFFu, s, o);
    if (lane == 0) g_csqh[code] = -0.5f * s;
}

// B chunk prefetch: chunk index cc -> stage cc%3
__device__ __forceinline__ void prefetch_chunk(uint32_t sb, int cc, int tid) {
    const int ct = cc >> 3, dcc = cc & 7;
    const char* src = reinterpret_cast<const char*>(
        g_cbT + (size_t)(dcc * DC) * KCODES + ct * CTILE);
    const uint32_t dst = sb + SM_B + (cc % 3) * BSTG;
#pragma unroll
    for (int k = 0; k < 8; k++) {
        int s = tid + k * 256;                 // 2048 x 16B
        int r = s >> 6, c = s & 63;
        CP16(dst + r * 1024 + c * 16, src + (size_t)r * (KCODES * 4) + c * 16);
    }
    CPCOMMIT();
}

// ---------------- main sweep ----------------
__global__ __launch_bounds__(256, 1) void sweep_kernel(const float* __restrict__ x) {
    extern __shared__ char sm[];
    float* Af     = reinterpret_cast<float*>(sm + SM_A);   // [d][112]
    float* csqh_s = reinterpret_cast<float*>(sm + SM_Q);
    u64*   sbest  = reinterpret_cast<u64*>(sm + SM_BEST);
    const uint32_t sb = smem_u32(sm);

    const int tid = threadIdx.x;
    const int tx  = tid & 15;       // code group (codes tx*4 + s*64 + q*2 .. +1)
    const int ty  = tid >> 4;       // token slot: tokens ty + 16*m, m<7
    const int n0  = blockIdx.x * MTILE;

    // ---- A fill: one d-row per thread, 28 x 16B cp.async, batch-split ----
    {
        const int pos0 = n0 & (HW - 1);
        const int b0   = n0 >> 10;
        const int len1 = min(MTILE, HW - pos0);          // multiple of 16
        const int d    = tid;
        const uint32_t dst = sb + SM_A + d * (MTILE * 4);
#pragma unroll
        for (int c = 0; c < 28; c++) {
            const int col0 = c * 4;                      // 4 tokens = 16 bytes
            if (col0 < len1) {
                const float* src = x + ((size_t)b0 * DIM + d) * HW + pos0 + col0;
                CP16(dst + col0 * 4, src);
            } else if (b0 + 1 < 16) {
                const float* src = x + ((size_t)(b0 + 1) * DIM + d) * HW + (col0 - len1);
                CP16(dst + col0 * 4, src);
            }
        }
        CPCOMMIT();
    }
    for (int i = tid; i < KCODES; i += 256) csqh_s[i] = g_csqh[i];
    if (tid < MTILE) sbest[tid] = 0ull;
    // ---- B prologue: chunks 0 and 1 ----
    prefetch_chunk(sb, 0, tid);
    prefetch_chunk(sb, 1, tid);

    float bestv[7];
    int   bestc[7];
#pragma unroll
    for (int i = 0; i < 7; i++) { bestv[i] = -3.4e38f; bestc[i] = 0; }

    u64 acc[7][8];

    for (int cidx = 0; cidx < NCHUNK; cidx++) {
        const int ct  = cidx >> 3;
        const int dcc = cidx & 7;

        // wait for chunk cidx (leave next one in flight), then one barrier:
        // makes chunk cidx visible AND proves all warps finished cidx-1,
        // whose stage (cidx+2)%3 we are about to overwrite.
        if (cidx + 1 < NCHUNK) CPWAIT1(); else CPWAIT0();
        __syncthreads();
        if (cidx + 2 < NCHUNK) prefetch_chunk(sb, cidx + 2, tid);

        // acc init at tile start: -0.5*||c||^2 pairs (codes tx*4 + s*64 + q*2)
        if (dcc == 0) {
            const int qb = ct * CTILE + tx * 4;
            u64 k8[8];
#pragma unroll
            for (int s = 0; s < 4; s++) {
                k8[s * 2]     = *reinterpret_cast<const u64*>(csqh_s + qb + s * 64);
                k8[s * 2 + 1] = *reinterpret_cast<const u64*>(csqh_s + qb + s * 64 + 2);
            }
#pragma unroll
            for (int i = 0; i < 7; i++)
#pragma unroll
                for (int j = 0; j < 8; j++) acc[i][j] = k8[j];
        }

        // ---- compute 32 d-steps ----
        const float*   Abase = Af + dcc * DC * MTILE + ty;
        const uint32_t Bbase = sb + SM_B + (cidx % 3) * BSTG + tx * 16;
#pragma unroll 4
        for (int k = 0; k < DC; k++) {
            u64 pa[7];
#pragma unroll
            for (int m = 0; m < 7; m++)
                pa[m] = pack2(Abase[k * MTILE + 16 * m]);
            u64 bb[8];
#pragma unroll
            for (int s = 0; s < 4; s++)
                lds_v2u64(bb[s * 2], bb[s * 2 + 1], Bbase + k * 1024 + s * 256);
#pragma unroll
            for (int i = 0; i < 7; i++)
#pragma unroll
                for (int j = 0; j < 8; j++)
                    fma2(acc[i][j], pa[i], bb[j]);
        }

        // ---- tile epilogue: running argmax ----
        if (dcc == 7) {
            const int cb0 = ct * CTILE + tx * 4;
#pragma unroll
            for (int i = 0; i < 7; i++)
#pragma unroll
                for (int s = 0; s < 4; s++)
#pragma unroll
                    for (int q = 0; q < 2; q++) {
                        unsigned lo, hi;
                        asm("mov.b64 {%0,%1}, %2;" : "=r"(lo), "=r"(hi) : "l"(acc[i][s * 2 + q]));
                        float v0 = __uint_as_float(lo), v1 = __uint_as_float(hi);
                        int c = cb0 + s * 64 + q * 2;
                        if (v0 > bestv[i]) { bestv[i] = v0; bestc[i] = c; }
                        if (v1 > bestv[i]) { bestv[i] = v1; bestc[i] = c + 1; }
                    }
        }
    }

    // ---- cross-thread reduction: max value, then min code ----
#pragma unroll
    for (int i = 0; i < 7; i++) {
        u64 key = ((u64)ford(bestv[i]) << 32) | (u64)(0xFFFFFFFFu - (unsigned)bestc[i]);
        atomicMax(&sbest[ty + 16 * i], key);
    }
    __syncthreads();
    if (tid < MTILE && n0 + tid < NTOK) {
        unsigned low = (unsigned)(sbest[tid] & 0xFFFFFFFFull);
        g_idx[n0 + tid] = (int)(0xFFFFFFFFu - low);
    }
}

// ---------------- gather ----------------
__global__ void gather_kernel(const float* __restrict__ cb, float* __restrict__ out) {
    int o = blockIdx.x * blockDim.x + threadIdx.x;
    int p = o & (HW - 1);
    int d = (o >> 10) & (DIM - 1);
    int b = o >> 18;
    int n = (b << 10) + p;
    out[o] = cb[(size_t)g_idx[n] * DIM + d];
}

extern "C" void kernel_launch(void* const* d_in, const int* in_sizes, int n_in,
                              void* d_out, int out_size) {
    const float* x  = (const float*)d_in[0];
    const float* cb = (const float*)d_in[1];
    float* out = (float*)d_out;

    cudaFuncSetAttribute(sweep_kernel, cudaFuncAttributeMaxDynamicSharedMemorySize, SM_TOT);

    tr_kernel<<<dim3(KCODES / 32, DIM / 32), 256>>>(cb);
    csqh_kernel<<<KCODES / 8, 256>>>(cb);
    sweep_kernel<<<NCTA, 256, SM_TOT>>>(x);
    gather_kernel<<<(NTOK * DIM) / 256, 256>>>(cb, out);
}

// round 10
// speedup vs baseline: 1.8206x; 1.0018x over previous
#include <cuda_runtime.h>
#include <stdint.h>

// ============================================================================
// Exact VQ argmin via packed fp32x2 FMA (SASS FFMA2, 2 MAC/instr).
// R10 = R9 (3-stage single-barrier B pipeline, 147 CTAs, DC=32) + vectorized
//       gather (float4 stores, 4x fewer threads/instructions).
//   prep:  cbT[d][code] transpose; csqh = -0.5*||c||^2
//   sweep: acc(init=csqh) += x*c via fma.rn.f32x2; argmax == argmin dist.
//   gather: out = codebook[idx], float4-vectorized
// ============================================================================

#define NTOK   16384
#define DIM    256
#define HW     1024
#define KCODES 4096
#define MTILE  112
#define NCTA   147              // ceil(16384/112)
#define CTILE  256              // codes per tile
#define DC     32               // dims per chunk
#define NCHUNK ((KCODES / CTILE) * (DIM / DC))   // 16 * 8 = 128
#define BSTG   32768            // one B stage: 32 d x 1024B

// smem (bytes)
#define SM_A    0                 // 256 d x 112 tok x 4B = 114688
#define SM_B    114688            // 3 x 32768 = 98304
#define SM_Q    212992            // csqh 4096 f32 = 16384
#define SM_BEST 229376            // 112 u64 (+pad)
#define SM_TOT  230400

__device__ float g_cbT[DIM * KCODES];   // [d][code]
__device__ float g_csqh[KCODES];        // -0.5*||c||^2
__device__ int   g_idx[NTOK];

typedef unsigned long long u64;
__device__ __forceinline__ uint32_t smem_u32(const void* p) {
    uint32_t a;
    asm("{ .reg .u64 t; cvta.to.shared.u64 t, %1; cvt.u32.u64 %0, t; }" : "=r"(a) : "l"(p));
    return a;
}
__device__ __forceinline__ unsigned ford(float f) {
    unsigned u = __float_as_uint(f);
    return (u & 0x80000000u) ? ~u : (u | 0x80000000u);
}
__device__ __forceinline__ u64 pack2(float v) {
    u64 r; unsigned b = __float_as_uint(v);
    asm("mov.b64 %0, {%1, %1};" : "=l"(r) : "r"(b));
    return r;
}
__device__ __forceinline__ void fma2(u64& acc, u64 a, u64 b) {
    asm("fma.rn.f32x2 %0, %1, %2, %0;" : "+l"(acc) : "l"(a), "l"(b));
}
__device__ __forceinline__ void lds_v2u64(u64& r0, u64& r1, uint32_t a) {
    asm volatile("ld.shared.v2.u64 {%0,%1}, [%2];" : "=l"(r0), "=l"(r1) : "r"(a));
}
#define CP16(d, s)  asm volatile("cp.async.cg.shared.global [%0], [%1], 16;" :: "r"(d), "l"(s))
#define CPCOMMIT()  asm volatile("cp.async.commit_group;" ::: "memory")
#define CPWAIT1()   asm volatile("cp.async.wait_group 1;" ::: "memory")
#define CPWAIT0()   asm volatile("cp.async.wait_group 0;" ::: "memory")

// ---------------- prep ----------------
__global__ __launch_bounds__(256) void tr_kernel(const float* __restrict__ cb) {
    __shared__ float t[32][33];
    const int c0 = blockIdx.x * 32, d0 = blockIdx.y * 32;
    const int tx = threadIdx.x & 31, ty8 = threadIdx.x >> 5;
#pragma unroll
    for (int r = 0; r < 4; r++)
        t[ty8 + r * 8][tx] = cb[(size_t)(c0 + ty8 + r * 8) * DIM + d0 + tx];
    __syncthreads();
#pragma unroll
    for (int r = 0; r < 4; r++)
        g_cbT[(size_t)(d0 + ty8 + r * 8) * KCODES + c0 + tx] = t[tx][ty8 + r * 8];
}
__global__ __launch_bounds__(256) void csqh_kernel(const float* __restrict__ cb) {
    const int code = blockIdx.x * 8 + (threadIdx.x >> 5);
    const int lane = threadIdx.x & 31;
    const float* row = cb + (size_t)code * DIM;
    float s = 0.f;
#pragma unroll
    for (int i = 0; i < 8; i++) { float v = row[lane + 32 * i]; s = fmaf(v, v, s); }
#pragma unroll
    for (int o = 16; o > 0; o >>= 1) s += __shfl_xor_sync(0xFFFFFFFFu, s, o);
    if (lane == 0) g_csqh[code] = -0.5f * s;
}

// B chunk prefetch: chunk index cc -> stage cc%3
__device__ __forceinline__ void prefetch_chunk(uint32_t sb, int cc, int tid) {
    const int ct = cc >> 3, dcc = cc & 7;
    const char* src = reinterpret_cast<const char*>(
        g_cbT + (size_t)(dcc * DC) * KCODES + ct * CTILE);
    const uint32_t dst = sb + SM_B + (cc % 3) * BSTG;
#pragma unroll
    for (int k = 0; k < 8; k++) {
        int s = tid + k * 256;                 // 2048 x 16B
        int r = s >> 6, c = s & 63;
        CP16(dst + r * 1024 + c * 16, src + (size_t)r * (KCODES * 4) + c * 16);
    }
    CPCOMMIT();
}

// ---------------- main sweep ----------------
__global__ __launch_bounds__(256, 1) void sweep_kernel(const float* __restrict__ x) {
    extern __shared__ char sm[];
    float* Af     = reinterpret_cast<float*>(sm + SM_A);   // [d][112]
    float* csqh_s = reinterpret_cast<float*>(sm + SM_Q);
    u64*   sbest  = reinterpret_cast<u64*>(sm + SM_BEST);
    const uint32_t sb = smem_u32(sm);

    const int tid = threadIdx.x;
    const int tx  = tid & 15;       // code group (codes tx*4 + s*64 + q*2 .. +1)
    const int ty  = tid >> 4;       // token slot: tokens ty + 16*m, m<7
    const int n0  = blockIdx.x * MTILE;

    // ---- A fill: one d-row per thread, 28 x 16B cp.async, batch-split ----
    {
        const int pos0 = n0 & (HW - 1);
        const int b0   = n0 >> 10;
        const int len1 = min(MTILE, HW - pos0);          // multiple of 16
        const int d    = tid;
        const uint32_t dst = sb + SM_A + d * (MTILE * 4);
#pragma unroll
        for (int c = 0; c < 28; c++) {
            const int col0 = c * 4;                      // 4 tokens = 16 bytes
            if (col0 < len1) {
                const float* src = x + ((size_t)b0 * DIM + d) * HW + pos0 + col0;
                CP16(dst + col0 * 4, src);
            } else if (b0 + 1 < 16) {
                const float* src = x + ((size_t)(b0 + 1) * DIM + d) * HW + (col0 - len1);
                CP16(dst + col0 * 4, src);
            }
        }
        CPCOMMIT();
    }
    for (int i = tid; i < KCODES; i += 256) csqh_s[i] = g_csqh[i];
    if (tid < MTILE) sbest[tid] = 0ull;
    // ---- B prologue: chunks 0 and 1 ----
    prefetch_chunk(sb, 0, tid);
    prefetch_chunk(sb, 1, tid);

    float bestv[7];
    int   bestc[7];
#pragma unroll
    for (int i = 0; i < 7; i++) { bestv[i] = -3.4e38f; bestc[i] = 0; }

    u64 acc[7][8];

    for (int cidx = 0; cidx < NCHUNK; cidx++) {
        const int ct  = cidx >> 3;
        const int dcc = cidx & 7;

        // wait for chunk cidx (leave next in flight); single barrier makes
        // chunk cidx visible AND proves all warps finished cidx-1, whose
        // stage (cidx+2)%3 we are about to overwrite.
        if (cidx + 1 < NCHUNK) CPWAIT1(); else CPWAIT0();
        __syncthreads();
        if (cidx + 2 < NCHUNK) prefetch_chunk(sb, cidx + 2, tid);

        // acc init at tile start: -0.5*||c||^2 pairs (codes tx*4 + s*64 + q*2)
        if (dcc == 0) {
            const int qb = ct * CTILE + tx * 4;
            u64 k8[8];
#pragma unroll
            for (int s = 0; s < 4; s++) {
                k8[s * 2]     = *reinterpret_cast<const u64*>(csqh_s + qb + s * 64);
                k8[s * 2 + 1] = *reinterpret_cast<const u64*>(csqh_s + qb + s * 64 + 2);
            }
#pragma unroll
            for (int i = 0; i < 7; i++)
#pragma unroll
                for (int j = 0; j < 8; j++) acc[i][j] = k8[j];
        }

        // ---- compute 32 d-steps ----
        const float*   Abase = Af + dcc * DC * MTILE + ty;
        const uint32_t Bbase = sb + SM_B + (cidx % 3) * BSTG + tx * 16;
#pragma unroll 4
        for (int k = 0; k < DC; k++) {
            u64 pa[7];
#pragma unroll
            for (int m = 0; m < 7; m++)
                pa[m] = pack2(Abase[k * MTILE + 16 * m]);
            u64 bb[8];
#pragma unroll
            for (int s = 0; s < 4; s++)
                lds_v2u64(bb[s * 2], bb[s * 2 + 1], Bbase + k * 1024 + s * 256);
#pragma unroll
            for (int i = 0; i < 7; i++)
#pragma unroll
                for (int j = 0; j < 8; j++)
                    fma2(acc[i][j], pa[i], bb[j]);
        }

        // ---- tile epilogue: running argmax ----
        if (dcc == 7) {
            const int cb0 = ct * CTILE + tx * 4;
#pragma unroll
            for (int i = 0; i < 7; i++)
#pragma unroll
                for (int s = 0; s < 4; s++)
#pragma unroll
                    for (int q = 0; q < 2; q++) {
                        unsigned lo, hi;
                        asm("mov.b64 {%0,%1}, %2;" : "=r"(lo), "=r"(hi) : "l"(acc[i][s * 2 + q]));
                        float v0 = __uint_as_float(lo), v1 = __uint_as_float(hi);
                        int c = cb0 + s * 64 + q * 2;
                        if (v0 > bestv[i]) { bestv[i] = v0; bestc[i] = c; }
                        if (v1 > bestv[i]) { bestv[i] = v1; bestc[i] = c + 1; }
                    }
        }
    }

    // ---- cross-thread reduction: max value, then min code ----
#pragma unroll
    for (int i = 0; i < 7; i++) {
        u64 key = ((u64)ford(bestv[i]) << 32) | (u64)(0xFFFFFFFFu - (unsigned)bestc[i]);
        atomicMax(&sbest[ty + 16 * i], key);
    }
    __syncthreads();
    if (tid < MTILE && n0 + tid < NTOK) {
        unsigned low = (unsigned)(sbest[tid] & 0xFFFFFFFFull);
        g_idx[n0 + tid] = (int)(0xFFFFFFFFu - low);
    }
}

// ---------------- gather: one float4 of output per thread ----------------
__global__ __launch_bounds__(256) void gather_kernel(const float* __restrict__ cb,
                                                     float* __restrict__ out) {
    const int o4 = blockIdx.x * blockDim.x + threadIdx.x;   // float4 index
    const int o  = o4 * 4;
    const int p  = o & (HW - 1);          // p..p+3 same d, same b
    const int d  = (o >> 10) & (DIM - 1);
    const int b  = o >> 18;
    const int n  = (b << 10) + p;
    float4 v;
    v.x = cb[(size_t)g_idx[n]     * DIM + d];
    v.y = cb[(size_t)g_idx[n + 1] * DIM + d];
    v.z = cb[(size_t)g_idx[n + 2] * DIM + d];
    v.w = cb[(size_t)g_idx[n + 3] * DIM + d];
    reinterpret_cast<float4*>(out)[o4] = v;
}

extern "C" void kernel_launch(void* const* d_in, const int* in_sizes, int n_in,
                              void* d_out, int out_size) {
    const float* x  = (const float*)d_in[0];
    const float* cb = (const float*)d_in[1];
    float* out = (float*)d_out;

    cudaFuncSetAttribute(sweep_kernel, cudaFuncAttributeMaxDynamicSharedMemorySize, SM_TOT);

    tr_kernel<<<dim3(KCODES / 32, DIM / 32), 256>>>(cb);
    csqh_kernel<<<KCODES / 8, 256>>>(cb);
    sweep_kernel<<<NCTA, 256, SM_TOT>>>(x);
    gather_kernel<<<(NTOK * DIM / 4) / 256, 256>>>(cb, out);
}

// round 11
// speedup vs baseline: 1.8444x; 1.0131x over previous
#include <cuda_runtime.h>
#include <stdint.h>

// ============================================================================
// Exact VQ argmin via packed fp32x2 FMA (SASS FFMA2, 2 MAC/instr).
// R11 = R10 sweep (3-stage single-barrier pipeline, 147 CTAs, DC=32)
//       + SMEM-staged gather: coalesced codebook-row reads -> smem ->
//         coalesced output-major float4 writes (kills scattered LDG.32).
// ============================================================================

#define NTOK   16384
#define DIM    256
#define HW     1024
#define KCODES 4096
#define MTILE  112
#define NCTA   147              // ceil(16384/112)
#define CTILE  256              // codes per tile
#define DC     32               // dims per chunk
#define NCHUNK ((KCODES / CTILE) * (DIM / DC))   // 16 * 8 = 128
#define BSTG   32768            // one B stage: 32 d x 1024B

// sweep smem (bytes)
#define SM_A    0                 // 256 d x 112 tok x 4B = 114688
#define SM_B    114688            // 3 x 32768 = 98304
#define SM_Q    212992            // csqh 4096 f32 = 16384
#define SM_BEST 229376            // 112 u64 (+pad)
#define SM_TOT  230400

// gather
#define GT      64                // tokens per gather CTA
#define GROW    257               // padded row stride (floats)
#define GSM_TOT (GT * GROW * 4 + 256)

__device__ float g_cbT[DIM * KCODES];   // [d][code]
__device__ float g_csqh[KCODES];        // -0.5*||c||^2
__device__ int   g_idx[NTOK];

typedef unsigned long long u64;
__device__ __forceinline__ uint32_t smem_u32(const void* p) {
    uint32_t a;
    asm("{ .reg .u64 t; cvta.to.shared.u64 t, %1; cvt.u32.u64 %0, t; }" : "=r"(a) : "l"(p));
    return a;
}
__device__ __forceinline__ unsigned ford(float f) {
    unsigned u = __float_as_uint(f);
    return (u & 0x80000000u) ? ~u : (u | 0x80000000u);
}
__device__ __forceinline__ u64 pack2(float v) {
    u64 r; unsigned b = __float_as_uint(v);
    asm("mov.b64 %0, {%1, %1};" : "=l"(r) : "r"(b));
    return r;
}
__device__ __forceinline__ void fma2(u64& acc, u64 a, u64 b) {
    asm("fma.rn.f32x2 %0, %1, %2, %0;" : "+l"(acc) : "l"(a), "l"(b));
}
__device__ __forceinline__ void lds_v2u64(u64& r0, u64& r1, uint32_t a) {
    asm volatile("ld.shared.v2.u64 {%0,%1}, [%2];" : "=l"(r0), "=l"(r1) : "r"(a));
}
#define CP16(d, s)  asm volatile("cp.async.cg.shared.global [%0], [%1], 16;" :: "r"(d), "l"(s))
#define CPCOMMIT()  asm volatile("cp.async.commit_group;" ::: "memory")
#define CPWAIT1()   asm volatile("cp.async.wait_group 1;" ::: "memory")
#define CPWAIT0()   asm volatile("cp.async.wait_group 0;" ::: "memory")

// ---------------- prep ----------------
__global__ __launch_bounds__(256) void tr_kernel(const float* __restrict__ cb) {
    __shared__ float t[32][33];
    const int c0 = blockIdx.x * 32, d0 = blockIdx.y * 32;
    const int tx = threadIdx.x & 31, ty8 = threadIdx.x >> 5;
#pragma unroll
    for (int r = 0; r < 4; r++)
        t[ty8 + r * 8][tx] = cb[(size_t)(c0 + ty8 + r * 8) * DIM + d0 + tx];
    __syncthreads();
#pragma unroll
    for (int r = 0; r < 4; r++)
        g_cbT[(size_t)(d0 + ty8 + r * 8) * KCODES + c0 + tx] = t[tx][ty8 + r * 8];
}
__global__ __launch_bounds__(256) void csqh_kernel(const float* __restrict__ cb) {
    const int code = blockIdx.x * 8 + (threadIdx.x >> 5);
    const int lane = threadIdx.x & 31;
    const float* row = cb + (size_t)code * DIM;
    float s = 0.f;
#pragma unroll
    for (int i = 0; i < 8; i++) { float v = row[lane + 32 * i]; s = fmaf(v, v, s); }
#pragma unroll
    for (int o = 16; o > 0; o >>= 1) s += __shfl_xor_sync(0xFFFFFFFFu, s, o);
    if (lane == 0) g_csqh[code] = -0.5f * s;
}

// B chunk prefetch: chunk index cc -> stage cc%3
__device__ __forceinline__ void prefetch_chunk(uint32_t sb, int cc, int tid) {
    const int ct = cc >> 3, dcc = cc & 7;
    const char* src = reinterpret_cast<const char*>(
        g_cbT + (size_t)(dcc * DC) * KCODES + ct * CTILE);
    const uint32_t dst = sb + SM_B + (cc % 3) * BSTG;
#pragma unroll
    for (int k = 0; k < 8; k++) {
        int s = tid + k * 256;                 // 2048 x 16B
        int r = s >> 6, c = s & 63;
        CP16(dst + r * 1024 + c * 16, src + (size_t)r * (KCODES * 4) + c * 16);
    }
    CPCOMMIT();
}

// ---------------- main sweep ----------------
__global__ __launch_bounds__(256, 1) void sweep_kernel(const float* __restrict__ x) {
    extern __shared__ char sm[];
    float* Af     = reinterpret_cast<float*>(sm + SM_A);   // [d][112]
    float* csqh_s = reinterpret_cast<float*>(sm + SM_Q);
    u64*   sbest  = reinterpret_cast<u64*>(sm + SM_BEST);
    const uint32_t sb = smem_u32(sm);

    const int tid = threadIdx.x;
    const int tx  = tid & 15;       // code group (codes tx*4 + s*64 + q*2 .. +1)
    const int ty  = tid >> 4;       // token slot: tokens ty + 16*m, m<7
    const int n0  = blockIdx.x * MTILE;

    // ---- A fill: one d-row per thread, 28 x 16B cp.async, batch-split ----
    {
        const int pos0 = n0 & (HW - 1);
        const int b0   = n0 >> 10;
        const int len1 = min(MTILE, HW - pos0);          // multiple of 16
        const int d    = tid;
        const uint32_t dst = sb + SM_A + d * (MTILE * 4);
#pragma unroll
        for (int c = 0; c < 28; c++) {
            const int col0 = c * 4;                      // 4 tokens = 16 bytes
            if (col0 < len1) {
                const float* src = x + ((size_t)b0 * DIM + d) * HW + pos0 + col0;
                CP16(dst + col0 * 4, src);
            } else if (b0 + 1 < 16) {
                const float* src = x + ((size_t)(b0 + 1) * DIM + d) * HW + (col0 - len1);
                CP16(dst + col0 * 4, src);
            }
        }
        CPCOMMIT();
    }
    for (int i = tid; i < KCODES; i += 256) csqh_s[i] = g_csqh[i];
    if (tid < MTILE) sbest[tid] = 0ull;
    // ---- B prologue: chunks 0 and 1 ----
    prefetch_chunk(sb, 0, tid);
    prefetch_chunk(sb, 1, tid);

    float bestv[7];
    int   bestc[7];
#pragma unroll
    for (int i = 0; i < 7; i++) { bestv[i] = -3.4e38f; bestc[i] = 0; }

    u64 acc[7][8];

    for (int cidx = 0; cidx < NCHUNK; cidx++) {
        const int ct  = cidx >> 3;
        const int dcc = cidx & 7;

        // wait for chunk cidx (leave next in flight); single barrier makes
        // chunk cidx visible AND proves all warps finished cidx-1, whose
        // stage (cidx+2)%3 we are about to overwrite.
        if (cidx + 1 < NCHUNK) CPWAIT1(); else CPWAIT0();
        __syncthreads();
        if (cidx + 2 < NCHUNK) prefetch_chunk(sb, cidx + 2, tid);

        // acc init at tile start: -0.5*||c||^2 pairs (codes tx*4 + s*64 + q*2)
        if (dcc == 0) {
            const int qb = ct * CTILE + tx * 4;
            u64 k8[8];
#pragma unroll
            for (int s = 0; s < 4; s++) {
                k8[s * 2]     = *reinterpret_cast<const u64*>(csqh_s + qb + s * 64);
                k8[s * 2 + 1] = *reinterpret_cast<const u64*>(csqh_s + qb + s * 64 + 2);
            }
#pragma unroll
            for (int i = 0; i < 7; i++)
#pragma unroll
                for (int j = 0; j < 8; j++) acc[i][j] = k8[j];
        }

        // ---- compute 32 d-steps ----
        const float*   Abase = Af + dcc * DC * MTILE + ty;
        const uint32_t Bbase = sb + SM_B + (cidx % 3) * BSTG + tx * 16;
#pragma unroll 4
        for (int k = 0; k < DC; k++) {
            u64 pa[7];
#pragma unroll
            for (int m = 0; m < 7; m++)
                pa[m] = pack2(Abase[k * MTILE + 16 * m]);
            u64 bb[8];
#pragma unroll
            for (int s = 0; s < 4; s++)
                lds_v2u64(bb[s * 2], bb[s * 2 + 1], Bbase + k * 1024 + s * 256);
#pragma unroll
            for (int i = 0; i < 7; i++)
#pragma unroll
                for (int j = 0; j < 8; j++)
                    fma2(acc[i][j], pa[i], bb[j]);
        }

        // ---- tile epilogue: running argmax ----
        if (dcc == 7) {
            const int cb0 = ct * CTILE + tx * 4;
#pragma unroll
            for (int i = 0; i < 7; i++)
#pragma unroll
                for (int s = 0; s < 4; s++)
#pragma unroll
                    for (int q = 0; q < 2; q++) {
                        unsigned lo, hi;
                        asm("mov.b64 {%0,%1}, %2;" : "=r"(lo), "=r"(hi) : "l"(acc[i][s * 2 + q]));
                        float v0 = __uint_as_float(lo), v1 = __uint_as_float(hi);
                        int c = cb0 + s * 64 + q * 2;
                        if (v0 > bestv[i]) { bestv[i] = v0; bestc[i] = c; }
                        if (v1 > bestv[i]) { bestv[i] = v1; bestc[i] = c + 1; }
                    }
        }
    }

    // ---- cross-thread reduction: max value, then min code ----
#pragma unroll
    for (int i = 0; i < 7; i++) {
        u64 key = ((u64)ford(bestv[i]) << 32) | (u64)(0xFFFFFFFFu - (unsigned)bestc[i]);
        atomicMax(&sbest[ty + 16 * i], key);
    }
    __syncthreads();
    if (tid < MTILE && n0 + tid < NTOK) {
        unsigned low = (unsigned)(sbest[tid] & 0xFFFFFFFFull);
        g_idx[n0 + tid] = (int)(0xFFFFFFFFu - low);
    }
}

// ---------------- gather: smem-staged, both gmem sides coalesced ----------
__global__ __launch_bounds__(256) void gather_kernel(const float* __restrict__ cb,
                                                     float* __restrict__ out) {
    extern __shared__ char gsm[];
    float* st  = reinterpret_cast<float*>(gsm);              // [GT][GROW]
    int* sidx  = reinterpret_cast<int*>(gsm + GT * GROW * 4);
    const int tid = threadIdx.x;
    const int n0  = blockIdx.x * GT;

    if (tid < GT) sidx[tid] = g_idx[n0 + tid];
    __syncthreads();

    // phase 1: stage selected codebook rows, coalesced float4 reads
#pragma unroll
    for (int k = 0; k < 16; k++) {
        const int e   = k * 1024 + tid * 4;       // element in [tok][d]
        const int tok = e >> 8, d = e & 255;
        const float4 v = *reinterpret_cast<const float4*>(
            cb + (size_t)sidx[tok] * DIM + d);
        st[tok * GROW + d + 0] = v.x;
        st[tok * GROW + d + 1] = v.y;
        st[tok * GROW + d + 2] = v.z;
        st[tok * GROW + d + 3] = v.w;
    }
    __syncthreads();

    // phase 2: output-major coalesced float4 stores
    const int b  = n0 >> 10;
    const int p0 = n0 & (HW - 1);
    float* ob = out + (size_t)b * DIM * HW + p0;
#pragma unroll
    for (int k = 0; k < 16; k++) {
        const int e4 = k * 256 + tid;             // d = e4/16, p-quad = e4%16
        const int d  = e4 >> 4;
        const int p  = (e4 & 15) * 4;
        float4 v;
        v.x = st[(p + 0) * GROW + d];
        v.y = st[(p + 1) * GROW + d];
        v.z = st[(p + 2) * GROW + d];
        v.w = st[(p + 3) * GROW + d];
        *reinterpret_cast<float4*>(ob + (size_t)d * HW + p) = v;
    }
}

extern "C" void kernel_launch(void* const* d_in, const int* in_sizes, int n_in,
                              void* d_out, int out_size) {
    const float* x  = (const float*)d_in[0];
    const float* cb = (const float*)d_in[1];
    float* out = (float*)d_out;

    cudaFuncSetAttribute(sweep_kernel, cudaFuncAttributeMaxDynamicSharedMemorySize, SM_TOT);
    cudaFuncSetAttribute(gather_kernel, cudaFuncAttributeMaxDynamicSharedMemorySize, GSM_TOT);

    tr_kernel<<<dim3(KCODES / 32, DIM / 32), 256>>>(cb);
    csqh_kernel<<<KCODES / 8, 256>>>(cb);
    sweep_kernel<<<NCTA, 256, SM_TOT>>>(x);
    gather_kernel<<<NTOK / GT, 256, GSM_TOT>>>(cb, out);
}

// round 12
// speedup vs baseline: 1.8494x; 1.0027x over previous
#include <cuda_runtime.h>
#include <stdint.h>

// ============================================================================
// Exact VQ argmin via packed fp32x2 FMA (SASS FFMA2, 2 MAC/instr).
// R12 = R11 sweep (untouched: 3-stage single-barrier pipeline, 147 CTAs,
//       DC=32) + gather with GT=32 (2x CTA residency) and MLP=8 phase-1 loads.
// ============================================================================

#define NTOK   16384
#define DIM    256
#define HW     1024
#define KCODES 4096
#define MTILE  112
#define NCTA   147              // ceil(16384/112)
#define CTILE  256              // codes per tile
#define DC     32               // dims per chunk
#define NCHUNK ((KCODES / CTILE) * (DIM / DC))   // 16 * 8 = 128
#define BSTG   32768            // one B stage: 32 d x 1024B

// sweep smem (bytes)
#define SM_A    0                 // 256 d x 112 tok x 4B = 114688
#define SM_B    114688            // 3 x 32768 = 98304
#define SM_Q    212992            // csqh 4096 f32 = 16384
#define SM_BEST 229376            // 112 u64 (+pad)
#define SM_TOT  230400

// gather
#define GT      32                // tokens per gather CTA
#define GROW    257               // padded row stride (floats)
#define GSM_TOT (GT * GROW * 4 + 256)

__device__ float g_cbT[DIM * KCODES];   // [d][code]
__device__ float g_csqh[KCODES];        // -0.5*||c||^2
__device__ int   g_idx[NTOK];

typedef unsigned long long u64;
__device__ __forceinline__ uint32_t smem_u32(const void* p) {
    uint32_t a;
    asm("{ .reg .u64 t; cvta.to.shared.u64 t, %1; cvt.u32.u64 %0, t; }" : "=r"(a) : "l"(p));
    return a;
}
__device__ __forceinline__ unsigned ford(float f) {
    unsigned u = __float_as_uint(f);
    return (u & 0x80000000u) ? ~u : (u | 0x80000000u);
}
__device__ __forceinline__ u64 pack2(float v) {
    u64 r; unsigned b = __float_as_uint(v);
    asm("mov.b64 %0, {%1, %1};" : "=l"(r) : "r"(b));
    return r;
}
__device__ __forceinline__ void fma2(u64& acc, u64 a, u64 b) {
    asm("fma.rn.f32x2 %0, %1, %2, %0;" : "+l"(acc) : "l"(a), "l"(b));
}
__device__ __forceinline__ void lds_v2u64(u64& r0, u64& r1, uint32_t a) {
    asm volatile("ld.shared.v2.u64 {%0,%1}, [%2];" : "=l"(r0), "=l"(r1) : "r"(a));
}
#define CP16(d, s)  asm volatile("cp.async.cg.shared.global [%0], [%1], 16;" :: "r"(d), "l"(s))
#define CPCOMMIT()  asm volatile("cp.async.commit_group;" ::: "memory")
#define CPWAIT1()   asm volatile("cp.async.wait_group 1;" ::: "memory")
#define CPWAIT0()   asm volatile("cp.async.wait_group 0;" ::: "memory")

// ---------------- prep ----------------
__global__ __launch_bounds__(256) void tr_kernel(const float* __restrict__ cb) {
    __shared__ float t[32][33];
    const int c0 = blockIdx.x * 32, d0 = blockIdx.y * 32;
    const int tx = threadIdx.x & 31, ty8 = threadIdx.x >> 5;
#pragma unroll
    for (int r = 0; r < 4; r++)
        t[ty8 + r * 8][tx] = cb[(size_t)(c0 + ty8 + r * 8) * DIM + d0 + tx];
    __syncthreads();
#pragma unroll
    for (int r = 0; r < 4; r++)
        g_cbT[(size_t)(d0 + ty8 + r * 8) * KCODES + c0 + tx] = t[tx][ty8 + r * 8];
}
__global__ __launch_bounds__(256) void csqh_kernel(const float* __restrict__ cb) {
    const int code = blockIdx.x * 8 + (threadIdx.x >> 5);
    const int lane = threadIdx.x & 31;
    const float* row = cb + (size_t)code * DIM;
    float s = 0.f;
#pragma unroll
    for (int i = 0; i < 8; i++) { float v = row[lane + 32 * i]; s = fmaf(v, v, s); }
#pragma unroll
    for (int o = 16; o > 0; o >>= 1) s += __shfl_xor_sync(0xFFFFFFFFu, s, o);
    if (lane == 0) g_csqh[code] = -0.5f * s;
}

// B chunk prefetch: chunk index cc -> stage cc%3
__device__ __forceinline__ void prefetch_chunk(uint32_t sb, int cc, int tid) {
    const int ct = cc >> 3, dcc = cc & 7;
    const char* src = reinterpret_cast<const char*>(
        g_cbT + (size_t)(dcc * DC) * KCODES + ct * CTILE);
    const uint32_t dst = sb + SM_B + (cc % 3) * BSTG;
#pragma unroll
    for (int k = 0; k < 8; k++) {
        int s = tid + k * 256;                 // 2048 x 16B
        int r = s >> 6, c = s & 63;
        CP16(dst + r * 1024 + c * 16, src + (size_t)r * (KCODES * 4) + c * 16);
    }
    CPCOMMIT();
}

// ---------------- main sweep ----------------
__global__ __launch_bounds__(256, 1) void sweep_kernel(const float* __restrict__ x) {
    extern __shared__ char sm[];
    float* Af     = reinterpret_cast<float*>(sm + SM_A);   // [d][112]
    float* csqh_s = reinterpret_cast<float*>(sm + SM_Q);
    u64*   sbest  = reinterpret_cast<u64*>(sm + SM_BEST);
    const uint32_t sb = smem_u32(sm);

    const int tid = threadIdx.x;
    const int tx  = tid & 15;       // code group (codes tx*4 + s*64 + q*2 .. +1)
    const int ty  = tid >> 4;       // token slot: tokens ty + 16*m, m<7
    const int n0  = blockIdx.x * MTILE;

    // ---- A fill: one d-row per thread, 28 x 16B cp.async, batch-split ----
    {
        const int pos0 = n0 & (HW - 1);
        const int b0   = n0 >> 10;
        const int len1 = min(MTILE, HW - pos0);          // multiple of 16
        const int d    = tid;
        const uint32_t dst = sb + SM_A + d * (MTILE * 4);
#pragma unroll
        for (int c = 0; c < 28; c++) {
            const int col0 = c * 4;                      // 4 tokens = 16 bytes
            if (col0 < len1) {
                const float* src = x + ((size_t)b0 * DIM + d) * HW + pos0 + col0;
                CP16(dst + col0 * 4, src);
            } else if (b0 + 1 < 16) {
                const float* src = x + ((size_t)(b0 + 1) * DIM + d) * HW + (col0 - len1);
                CP16(dst + col0 * 4, src);
            }
        }
        CPCOMMIT();
    }
    for (int i = tid; i < KCODES; i += 256) csqh_s[i] = g_csqh[i];
    if (tid < MTILE) sbest[tid] = 0ull;
    // ---- B prologue: chunks 0 and 1 ----
    prefetch_chunk(sb, 0, tid);
    prefetch_chunk(sb, 1, tid);

    float bestv[7];
    int   bestc[7];
#pragma unroll
    for (int i = 0; i < 7; i++) { bestv[i] = -3.4e38f; bestc[i] = 0; }

    u64 acc[7][8];

    for (int cidx = 0; cidx < NCHUNK; cidx++) {
        const int ct  = cidx >> 3;
        const int dcc = cidx & 7;

        // wait for chunk cidx (leave next in flight); single barrier makes
        // chunk cidx visible AND proves all warps finished cidx-1, whose
        // stage (cidx+2)%3 we are about to overwrite.
        if (cidx + 1 < NCHUNK) CPWAIT1(); else CPWAIT0();
        __syncthreads();
        if (cidx + 2 < NCHUNK) prefetch_chunk(sb, cidx + 2, tid);

        // acc init at tile start: -0.5*||c||^2 pairs (codes tx*4 + s*64 + q*2)
        if (dcc == 0) {
            const int qb = ct * CTILE + tx * 4;
            u64 k8[8];
#pragma unroll
            for (int s = 0; s < 4; s++) {
                k8[s * 2]     = *reinterpret_cast<const u64*>(csqh_s + qb + s * 64);
                k8[s * 2 + 1] = *reinterpret_cast<const u64*>(csqh_s + qb + s * 64 + 2);
            }
#pragma unroll
            for (int i = 0; i < 7; i++)
#pragma unroll
                for (int j = 0; j < 8; j++) acc[i][j] = k8[j];
        }

        // ---- compute 32 d-steps ----
        const float*   Abase = Af + dcc * DC * MTILE + ty;
        const uint32_t Bbase = sb + SM_B + (cidx % 3) * BSTG + tx * 16;
#pragma unroll 4
        for (int k = 0; k < DC; k++) {
            u64 pa[7];
#pragma unroll
            for (int m = 0; m < 7; m++)
                pa[m] = pack2(Abase[k * MTILE + 16 * m]);
            u64 bb[8];
#pragma unroll
            for (int s = 0; s < 4; s++)
                lds_v2u64(bb[s * 2], bb[s * 2 + 1], Bbase + k * 1024 + s * 256);
#pragma unroll
            for (int i = 0; i < 7; i++)
#pragma unroll
                for (int j = 0; j < 8; j++)
                    fma2(acc[i][j], pa[i], bb[j]);
        }

        // ---- tile epilogue: running argmax ----
        if (dcc == 7) {
            const int cb0 = ct * CTILE + tx * 4;
#pragma unroll
            for (int i = 0; i < 7; i++)
#pragma unroll
                for (int s = 0; s < 4; s++)
#pragma unroll
                    for (int q = 0; q < 2; q++) {
                        unsigned lo, hi;
                        asm("mov.b64 {%0,%1}, %2;" : "=r"(lo), "=r"(hi) : "l"(acc[i][s * 2 + q]));
                        float v0 = __uint_as_float(lo), v1 = __uint_as_float(hi);
                        int c = cb0 + s * 64 + q * 2;
                        if (v0 > bestv[i]) { bestv[i] = v0; bestc[i] = c; }
                        if (v1 > bestv[i]) { bestv[i] = v1; bestc[i] = c + 1; }
                    }
        }
    }

    // ---- cross-thread reduction: max value, then min code ----
#pragma unroll
    for (int i = 0; i < 7; i++) {
        u64 key = ((u64)ford(bestv[i]) << 32) | (u64)(0xFFFFFFFFu - (unsigned)bestc[i]);
        atomicMax(&sbest[ty + 16 * i], key);
    }
    __syncthreads();
    if (tid < MTILE && n0 + tid < NTOK) {
        unsigned low = (unsigned)(sbest[tid] & 0xFFFFFFFFull);
        g_idx[n0 + tid] = (int)(0xFFFFFFFFu - low);
    }
}

// ---------------- gather: smem-staged, GT=32, MLP=8 phase-1 ----------------
__global__ __launch_bounds__(256) void gather_kernel(const float* __restrict__ cb,
                                                     float* __restrict__ out) {
    extern __shared__ char gsm[];
    float* st  = reinterpret_cast<float*>(gsm);              // [GT][GROW]
    int* sidx  = reinterpret_cast<int*>(gsm + GT * GROW * 4);
    const int tid = threadIdx.x;
    const int n0  = blockIdx.x * GT;

    if (tid < GT) sidx[tid] = g_idx[n0 + tid];
    __syncthreads();

    // phase 1: stage selected codebook rows; 8 independent LDG.128 in flight
    {
        float4 v[8];
#pragma unroll
        for (int k = 0; k < 8; k++) {
            const int e   = k * 1024 + tid * 4;   // element in [tok][d]
            const int tok = e >> 8, d = e & 255;
            v[k] = *reinterpret_cast<const float4*>(cb + (size_t)sidx[tok] * DIM + d);
        }
#pragma unroll
        for (int k = 0; k < 8; k++) {
            const int e   = k * 1024 + tid * 4;
            const int tok = e >> 8, d = e & 255;
            st[tok * GROW + d + 0] = v[k].x;
            st[tok * GROW + d + 1] = v[k].y;
            st[tok * GROW + d + 2] = v[k].z;
            st[tok * GROW + d + 3] = v[k].w;
        }
    }
    __syncthreads();

    // phase 2: output-major coalesced float4 stores (8 p-quads per d-row)
    const int b  = n0 >> 10;
    const int p0 = n0 & (HW - 1);
    float* ob = out + (size_t)b * DIM * HW + p0;
#pragma unroll
    for (int k = 0; k < 8; k++) {
        const int e4 = k * 256 + tid;             // d = e4/8, p-quad = e4%8
        const int d  = e4 >> 3;
        const int p  = (e4 & 7) * 4;
        float4 v;
        v.x = st[(p + 0) * GROW + d];
        v.y = st[(p + 1) * GROW + d];
        v.z = st[(p + 2) * GROW + d];
        v.w = st[(p + 3) * GROW + d];
        *reinterpret_cast<float4*>(ob + (size_t)d * HW + p) = v;
    }
}

extern "C" void kernel_launch(void* const* d_in, const int* in_sizes, int n_in,
                              void* d_out, int out_size) {
    const float* x  = (const float*)d_in[0];
    const float* cb = (const float*)d_in[1];
    float* out = (float*)d_out;

    cudaFuncSetAttribute(sweep_kernel, cudaFuncAttributeMaxDynamicSharedMemorySize, SM_TOT);
    cudaFuncSetAttribute(gather_kernel, cudaFuncAttributeMaxDynamicSharedMemorySize, GSM_TOT);

    tr_kernel<<<dim3(KCODES / 32, DIM / 32), 256>>>(cb);
    csqh_kernel<<<KCODES / 8, 256>>>(cb);
    sweep_kernel<<<NCTA, 256, SM_TOT>>>(x);
    gather_kernel<<<NTOK / GT, 256, GSM_TOT>>>(cb, out);
}